// round 9
// baseline (speedup 1.0000x reference)
#include <cuda_runtime.h>
#include <cstdint>

#define B_ 256
#define T_ 1024
#define D_ 64
#define H_ 100
#define G_ 400   // 4*H
#define NBLK 128
#define L2E 1.44269504088896f

// Precomputed input-gate contributions (bias included), PERMUTED row order:
// xg[b][t][p] holds gate-row ((p&3)*H + (p>>2)).  ~419 MB.
__device__ float g_xg[(size_t)B_ * T_ * G_];

// ---------------------------------------------------------------------------
// Packed f32x2 helpers
// ---------------------------------------------------------------------------
__device__ __forceinline__ unsigned long long ffma2(unsigned long long a,
                                                    unsigned long long b,
                                                    unsigned long long c) {
    unsigned long long d;
    asm("fma.rn.f32x2 %0, %1, %2, %3;" : "=l"(d) : "l"(a), "l"(b), "l"(c));
    return d;
}
__device__ __forceinline__ unsigned long long add2(unsigned long long a,
                                                   unsigned long long b) {
    unsigned long long d;
    asm("add.rn.f32x2 %0, %1, %2;" : "=l"(d) : "l"(a), "l"(b));
    return d;
}
__device__ __forceinline__ unsigned long long pack2(float x, float y) {
    return ((unsigned long long)__float_as_uint(y) << 32) |
           (unsigned long long)__float_as_uint(x);
}
__device__ __forceinline__ float lo2(unsigned long long v) {
    return __uint_as_float((unsigned)v);
}
__device__ __forceinline__ float hi2(unsigned long long v) {
    return __uint_as_float((unsigned)(v >> 32));
}
__device__ __forceinline__ float ex2a(float x) {
    float r; asm("ex2.approx.ftz.f32 %0, %1;" : "=f"(r) : "f"(x)); return r;
}
__device__ __forceinline__ float rcpa(float x) {
    float r; asm("rcp.approx.ftz.f32 %0, %1;" : "=f"(r) : "f"(x)); return r;
}
// sigmoid(x) = 1 - 1/(e^x+1)  (lm=log2e, s=1);  tanh(x) = 1 - 2/(e^2x+1)
__device__ __forceinline__ float uact(float x, float lm, float s) {
    return 1.0f - s * rcpa(ex2a(lm * x) + 1.0f);
}

// ---------------------------------------------------------------------------
// Kernel 1: xg[b,t,p] = x[b,t,:] . W_ih[row,:] + (b_ih+b_hh)[row],
//           row = (p&3)*H + (p>>2).  (R1 structure — fastest measured.)
// ---------------------------------------------------------------------------
__global__ __launch_bounds__(512, 1)
void xg_kernel(const float* __restrict__ x,
               const float* __restrict__ W_ih,
               const float* __restrict__ b_ih,
               const float* __restrict__ b_hh) {
    __shared__ ulonglong2 xs[64][16];   // 64 t x 64 k fp32 tile (16 KB)

    const int b   = blockIdx.y;
    const int t0  = blockIdx.x * 64;
    const int tid = threadIdx.x;

    {   // coalesced float4 tile load
        const float4* src = (const float4*)(x + ((size_t)b * T_ + t0) * D_);
        float4* dst = (float4*)xs;
        for (int i = tid; i < 64 * 16; i += 512) dst[i] = src[i];
    }

    unsigned long long w2[32];
    float bias = 0.0f;
    if (tid < G_) {
        const int row = (tid & 3) * H_ + (tid >> 2);
        const float4* wrow = (const float4*)(W_ih + (size_t)row * D_);
#pragma unroll
        for (int i = 0; i < 16; i++) {
            float4 v = wrow[i];
            w2[2 * i]     = pack2(v.x, v.y);
            w2[2 * i + 1] = pack2(v.z, v.w);
        }
        bias = b_ih[row] + b_hh[row];
    }
    __syncthreads();

    if (tid < G_) {
        float* out = g_xg + ((size_t)b * T_ + t0) * G_ + tid;
#pragma unroll 2
        for (int t = 0; t < 64; t++) {
            unsigned long long a0 = 0ull, a1 = 0ull;
#pragma unroll
            for (int i = 0; i < 16; i++) {
                ulonglong2 xv = xs[t][i];          // broadcast LDS.128
                a0 = ffma2(w2[2 * i],     xv.x, a0);
                a1 = ffma2(w2[2 * i + 1], xv.y, a1);
            }
            unsigned long long s2 = add2(a0, a1);
            out[(size_t)t * G_] = lo2(s2) + hi2(s2) + bias;
        }
    }
}

// ---------------------------------------------------------------------------
// Kernel 2: recurrence, RATIO-4 layout. 128 blocks x 2 batch rows, 800 thr.
// Thread: rp = tid>>2 (row-pair: permuted rows 2rp,2rp+1 = gates {0,1} or
// {2,3} of unit j=rp>>1), q = tid&3 (k-quarter of 50 pairs: 13/12/13/12).
// One LDS.128 (dual-batch h quad) feeds FOUR FFMA2 (2 rows x 2 batches):
// 13 LDS + 52 FFMA2 per thread per step.  Combine: shfl_xor butterfly over
// the 4 q-lanes; each lane activates one (gate,batch); gather {f,g,o} via
// shfl_down 2/4/6 (8-lane unit group); gate-0 lanes own c.  ONE barrier/step.
// ---------------------------------------------------------------------------
__global__ __launch_bounds__(800, 1)
void lstm_kernel(const float* __restrict__ h0,
                 const float* __restrict__ c0,
                 const float* __restrict__ W_hh,
                 const float* __restrict__ W_fc,
                 const float* __restrict__ b_fc,
                 float* __restrict__ out) {
    __shared__ float4 hs4[2][50];      // [buf][pair i]={h0_2i,h0_2i+1,h1_2i,h1_2i+1}
    __shared__ float wfc_s[H_];

    const int tid    = threadIdx.x;
    const int batch0 = blockIdx.x * 2;
    const int rp     = tid >> 2;       // row-pair (0..199)
    const int q      = tid & 3;        // k-quarter
    const int j      = rp >> 1;        // hidden unit
    const int ghalf  = rp & 1;         // 0: gates{0,1}, 1: gates{2,3}
    const int r0     = 2 * ghalf * H_ + j;   // actual W row of permuted 2rp
    const int r1     = r0 + H_;              // row of permuted 2rp+1

    // k-quarter pair ranges over the 50 pairs
    const int lo_t[4] = {0, 13, 25, 38};
    const int hi_t[4] = {13, 25, 38, 50};
    const int lo = lo_t[q], hi = hi_t[q];

    // --- init h buffer 0, wfc ---
    if (tid < H_) {
        int i = tid >> 1, comp = tid & 1;
        ((float*)&hs4[0][i])[comp]     = h0[(size_t)(batch0)     * H_ + tid];
        ((float*)&hs4[0][i])[2 + comp] = h0[(size_t)(batch0 + 1) * H_ + tid];
        wfc_s[tid] = W_fc[tid];
    }

    // --- weights: pairs [lo,hi) of rows r0, r1; zero-padded to 13 ---
    unsigned long long w2a[13], w2b[13];
    {
        const float2* wr0 = (const float2*)(W_hh + (size_t)r0 * H_);
        const float2* wr1 = (const float2*)(W_hh + (size_t)r1 * H_);
#pragma unroll
        for (int i = 0; i < 13; i++) {
            int idx = lo + i;
            if (idx < hi) {
                float2 v0 = wr0[idx], v1 = wr1[idx];
                w2a[i] = pack2(v0.x, v0.y);
                w2b[i] = pack2(v1.x, v1.y);
            } else {
                w2a[i] = 0ull;
                w2b[i] = 0ull;
            }
        }
    }

    // This lane activates (gate_act, b_act) of unit j
    const int  b_act    = q & 1;
    const int  gate_act = 2 * ghalf + (q >> 1);
    const float lm = (gate_act == 2) ? 2.0f * L2E : L2E;
    const float sc = (gate_act == 2) ? 2.0f : 1.0f;
    const int  p_act = 2 * rp + (q >> 1);      // permuted row of my value

    // c owned by (ghalf==0, q<2) lanes: (unit j, batch q)
    const bool owner = (ghalf == 0) && (q < 2);
    float cr = owner ? c0[(size_t)(batch0 + q) * H_ + j] : 0.0f;

    // xg stream (bias included) for my (batch, permuted row)
    const float* xp = g_xg + (size_t)(batch0 + b_act) * T_ * G_ + p_act;
    float xgc = xp[0];

    __syncthreads();

    int cur = 0;
    for (int t = 0; t < T_; t++) {
        float xgn = (t + 1 < T_) ? xp[(size_t)(t + 1) * G_] : 0.0f;  // prefetch

        // ratio-4 matvec: 13 LDS.128 -> 52 FFMA2
        unsigned long long A00 = 0ull, A01 = 0ull, A10 = 0ull, A11 = 0ull;
        const float4* hb = hs4[cur];
#pragma unroll
        for (int i = 0; i < 13; i++) {
            int idx = lo + i;
            if (idx > 49) idx = 49;              // clamp (zero weight there)
            float4 hv = hb[idx];                 // LDS.128, 4 addrs/warp, no conflict
            unsigned long long h0p = pack2(hv.x, hv.y);
            unsigned long long h1p = pack2(hv.z, hv.w);
            A00 = ffma2(w2a[i], h0p, A00);       // row0, batch0
            A01 = ffma2(w2a[i], h1p, A01);       // row0, batch1
            A10 = ffma2(w2b[i], h0p, A10);       // row1, batch0
            A11 = ffma2(w2b[i], h1p, A11);       // row1, batch1
        }
        float s00 = lo2(A00) + hi2(A00);
        float s01 = lo2(A01) + hi2(A01);
        float s10 = lo2(A10) + hi2(A10);
        float s11 = lo2(A11) + hi2(A11);

        // butterfly over the 4 q-lanes: full sums in every lane
        s00 += __shfl_xor_sync(0xffffffffu, s00, 1);
        s01 += __shfl_xor_sync(0xffffffffu, s01, 1);
        s10 += __shfl_xor_sync(0xffffffffu, s10, 1);
        s11 += __shfl_xor_sync(0xffffffffu, s11, 1);
        s00 += __shfl_xor_sync(0xffffffffu, s00, 2);
        s01 += __shfl_xor_sync(0xffffffffu, s01, 2);
        s10 += __shfl_xor_sync(0xffffffffu, s10, 2);
        s11 += __shfl_xor_sync(0xffffffffu, s11, 2);

        // my value: row_sel = q>>1, batch = q&1
        float va = (q & 2) ? ((q & 1) ? s11 : s10)
                           : ((q & 1) ? s01 : s00);
        float gv = uact(va + xgc, lm, sc);       // activated gate

        // unit-group layout (8 lanes): o = 4*ghalf + q ->
        //   {i b0, i b1, f b0, f b1, g b0, g b1, o b0, o b1}
        float fv = __shfl_down_sync(0xffffffffu, gv, 2);
        float gg = __shfl_down_sync(0xffffffffu, gv, 4);
        float ov = __shfl_down_sync(0xffffffffu, gv, 6);

        if (owner) {                             // (unit j, batch q)
            cr = fv * cr + gv * gg;
            float hv = ov * uact(cr, 2.0f * L2E, 2.0f);
            ((float*)&hs4[cur ^ 1][j >> 1])[(j & 1) + 2 * q] = hv;
        }
        xgc = xgn;
        __syncthreads();
        cur ^= 1;
    }

    // FC head: out[b] = h_T . W_fc + b_fc   (h_T in hs4[cur])
    if (tid < 2) {
        float acc = b_fc[0];
#pragma unroll 4
        for (int jj = 0; jj < H_; jj++) {
            float hv = ((const float*)&hs4[cur][jj >> 1])[(jj & 1) + 2 * tid];
            acc += hv * wfc_s[jj];
        }
        out[batch0 + tid] = acc;
    }
}

// ---------------------------------------------------------------------------
extern "C" void kernel_launch(void* const* d_in, const int* in_sizes, int n_in,
                              void* d_out, int out_size) {
    const float* x    = (const float*)d_in[0];
    const float* h0   = (const float*)d_in[1];
    const float* c0   = (const float*)d_in[2];
    const float* W_ih = (const float*)d_in[3];
    const float* W_hh = (const float*)d_in[4];
    const float* b_ih = (const float*)d_in[5];
    const float* b_hh = (const float*)d_in[6];
    const float* W_fc = (const float*)d_in[7];
    const float* b_fc = (const float*)d_in[8];
    float* out = (float*)d_out;

    dim3 grid1(T_ / 64, B_);
    xg_kernel<<<grid1, 512>>>(x, W_ih, b_ih, b_hh);

    lstm_kernel<<<NBLK, 800>>>(h0, c0, W_hh, W_fc, b_fc, out);
}

// round 10
// speedup vs baseline: 1.7377x; 1.7377x over previous
#include <cuda_runtime.h>
#include <cstdint>

#define B_ 256
#define T_ 1024
#define D_ 64
#define H_ 100
#define G_ 400   // 4*H

// Precomputed input-gate contributions (bias included), row-major:
// xg[b][t][row], row = gate*H + j  (matches R1 lstm).  ~419 MB.
__device__ float g_xg[(size_t)B_ * T_ * G_];

// ---------------------------------------------------------------------------
// Packed f32x2 helpers
// ---------------------------------------------------------------------------
__device__ __forceinline__ unsigned long long ffma2(unsigned long long a,
                                                    unsigned long long b,
                                                    unsigned long long c) {
    unsigned long long d;
    asm("fma.rn.f32x2 %0, %1, %2, %3;" : "=l"(d) : "l"(a), "l"(b), "l"(c));
    return d;
}
__device__ __forceinline__ unsigned long long pack2(float x, float y) {
    return ((unsigned long long)__float_as_uint(y) << 32) |
           (unsigned long long)__float_as_uint(x);
}
__device__ __forceinline__ float lo2(unsigned long long v) {
    return __uint_as_float((unsigned)v);
}
__device__ __forceinline__ float hi2(unsigned long long v) {
    return __uint_as_float((unsigned)(v >> 32));
}
__device__ __forceinline__ float sig_f(float x) {
    return __fdividef(1.0f, 1.0f + __expf(-x));
}
__device__ __forceinline__ float tanh_f(float x) {
    return 1.0f - __fdividef(2.0f, __expf(2.0f * x) + 1.0f);
}

// ---------------------------------------------------------------------------
// Kernel 1 (v3): xg[b,t,row] = x[b,t,:] . W_ih[row,:] + (b_ih+b_hh)[row]
// 2-D register tiling: thread = (row-quad rq, t-oct tq). Per k-pair:
//   2 LDS.128 -> weights of 4 rows, 4 LDS.128 (broadcast) -> x of 8 t,
//   32 FFMA2.  Ratio-8; no persistent weight registers.
// t-tile 128 per block, 4 passes of 32 t. Grid (8, 256).
// ---------------------------------------------------------------------------
#define TT 128
#define WKS 402    // ULL stride per k-pair row of W smem (3216B = 201*16)
#define XTS 130    // ULL stride per k-pair row of x smem (1040B = 65*16)
#define XG_SMEM_W  (32 * WKS * 8)            // 102912 B
#define XG_SMEM_X  (32 * XTS * 8)            //  33280 B
#define XG_SMEM    (XG_SMEM_W + XG_SMEM_X)   // 136192 B

__global__ __launch_bounds__(400, 1)
void xg_kernel(const float* __restrict__ x,
               const float* __restrict__ W_ih,
               const float* __restrict__ b_ih,
               const float* __restrict__ b_hh) {
    extern __shared__ char smem[];
    unsigned long long* wk2 = (unsigned long long*)(smem);             // [kp][row]
    unsigned long long* xt2 = (unsigned long long*)(smem + XG_SMEM_W); // [kp][t]

    const int b   = blockIdx.y;
    const int t0  = blockIdx.x * TT;
    const int tid = threadIdx.x;
    const int rq  = tid % 100;     // row-quad: rows 4rq..4rq+3
    const int tq  = tid / 100;     // 0..3

    // ---- W_ih (400x64) -> wk2[kp][row] (coalesced LDG, strided STS) ----
    const float4* wsrc = (const float4*)W_ih;          // 6400 chunks
#pragma unroll
    for (int it = 0; it < 16; it++) {
        int f = tid + it * 400;
        float4 v = wsrc[f];
        int r   = f >> 4;                              // row
        int kp0 = (f & 15) * 2;                        // k-pair
        wk2[(size_t)kp0 * WKS + r]       = pack2(v.x, v.y);
        wk2[(size_t)(kp0 + 1) * WKS + r] = pack2(v.z, v.w);
    }
    // ---- x tile (128t x 64k) -> xt2[kp][t] (transposed) ----
    const float4* xsrc = (const float4*)(x + ((size_t)b * T_ + t0) * D_);
#pragma unroll
    for (int it = 0; it < 6; it++) {                   // 2048 chunks / 400
        int f = tid + it * 400;
        if (f < TT * 16) {
            float4 v = xsrc[f];
            int t   = f >> 4;
            int kp0 = (f & 15) * 2;
            xt2[(size_t)kp0 * XTS + t]       = pack2(v.x, v.y);
            xt2[(size_t)(kp0 + 1) * XTS + t] = pack2(v.z, v.w);
        }
    }
    float4 ba = ((const float4*)b_ih)[rq];
    float4 bb = ((const float4*)b_hh)[rq];
    const float bias[4] = {ba.x + bb.x, ba.y + bb.y, ba.z + bb.z, ba.w + bb.w};
    __syncthreads();

    for (int s = 0; s < 4; s++) {
        const int tb = s * 32 + tq * 8;                // my 8-t window
        unsigned long long acc[8][4];
#pragma unroll
        for (int t = 0; t < 8; t++)
#pragma unroll
            for (int p = 0; p < 4; p++) acc[t][p] = 0ull;

#pragma unroll
        for (int kp = 0; kp < 32; kp++) {
            const unsigned long long* wrow = wk2 + (size_t)kp * WKS + 4 * rq;
            ulonglong2 wA = *(const ulonglong2*)(wrow);       // rows 4rq,4rq+1
            ulonglong2 wB = *(const ulonglong2*)(wrow + 2);   // rows 4rq+2,+3
            const unsigned long long* xrow = xt2 + (size_t)kp * XTS + tb;
            ulonglong2 xA = *(const ulonglong2*)(xrow);       // t 0,1 (bcast)
            ulonglong2 xB = *(const ulonglong2*)(xrow + 2);
            ulonglong2 xC = *(const ulonglong2*)(xrow + 4);
            ulonglong2 xD = *(const ulonglong2*)(xrow + 6);
            unsigned long long wv[4] = {wA.x, wA.y, wB.x, wB.y};
            unsigned long long xv[8] = {xA.x, xA.y, xB.x, xB.y,
                                        xC.x, xC.y, xD.x, xD.y};
#pragma unroll
            for (int t = 0; t < 8; t++)
#pragma unroll
                for (int p = 0; p < 4; p++)
                    acc[t][p] = ffma2(wv[p], xv[t], acc[t][p]);
        }

        float* outp = g_xg + ((size_t)b * T_ + t0 + tb) * G_ + 4 * rq;
#pragma unroll
        for (int t = 0; t < 8; t++) {
            float4 o;
            o.x = lo2(acc[t][0]) + hi2(acc[t][0]) + bias[0];
            o.y = lo2(acc[t][1]) + hi2(acc[t][1]) + bias[1];
            o.z = lo2(acc[t][2]) + hi2(acc[t][2]) + bias[2];
            o.w = lo2(acc[t][3]) + hi2(acc[t][3]) + bias[3];
            *(float4*)(outp + (size_t)t * G_) = o;
        }
    }
}

// ---------------------------------------------------------------------------
// Kernel 2: recurrence — R1 version verbatim (best measured: 1.109 ms).
// 128 blocks x 2 batch rows, 416 threads; thread tid<400 owns W_hh row tid
// (50 packed f32x2 regs), h in shared ulonglong2, gbuf 2-phase, 2 barriers.
// ---------------------------------------------------------------------------
__global__ __launch_bounds__(416, 1)
void lstm_kernel(const float* __restrict__ h0,
                 const float* __restrict__ c0,
                 const float* __restrict__ W_hh,
                 const float* __restrict__ W_fc,
                 const float* __restrict__ b_fc,
                 float* __restrict__ out) {
    __shared__ ulonglong2 hs[2][25];     // 2 x 100 floats (h per batch row)
    __shared__ float gbuf[2][G_];        // activated gates
    __shared__ float wfc_s[H_];

    const int tid    = threadIdx.x;
    const int batch0 = blockIdx.x * 2;

    float c = 0.0f;
    if (tid < 2 * H_) {
        const int b = tid / H_, j = tid - b * H_;
        ((float*)hs[b])[j] = h0[(size_t)(batch0 + b) * H_ + j];
        c = c0[(size_t)(batch0 + b) * H_ + j];
    }
    if (tid < H_) wfc_s[tid] = W_fc[tid];

    unsigned long long w2[50];
    if (tid < G_) {
        const float4* wrow = (const float4*)(W_hh + (size_t)tid * H_);
#pragma unroll
        for (int i = 0; i < 25; i++) {
            float4 v = wrow[i];
            w2[2 * i]     = pack2(v.x, v.y);
            w2[2 * i + 1] = pack2(v.z, v.w);
        }
    }

    const float* xg0 = g_xg + (size_t)(batch0)     * T_ * G_ + tid;
    const float* xg1 = g_xg + (size_t)(batch0 + 1) * T_ * G_ + tid;
    float xgc0 = 0.0f, xgc1 = 0.0f;
    if (tid < G_) { xgc0 = xg0[0]; xgc1 = xg1[0]; }

    __syncthreads();

    for (int t = 0; t < T_; t++) {
        float xgn0 = 0.0f, xgn1 = 0.0f;
        if (tid < G_ && t + 1 < T_) {
            xgn0 = xg0[(size_t)(t + 1) * G_];
            xgn1 = xg1[(size_t)(t + 1) * G_];
        }

        if (tid < G_) {
            unsigned long long a0 = 0ull, a1 = 0ull, b0 = 0ull, b1 = 0ull;
#pragma unroll
            for (int i = 0; i < 25; i++) {
                ulonglong2 hv = hs[0][i];
                a0 = ffma2(w2[2 * i],     hv.x, a0);
                a1 = ffma2(w2[2 * i + 1], hv.y, a1);
            }
#pragma unroll
            for (int i = 0; i < 25; i++) {
                ulonglong2 hv = hs[1][i];
                b0 = ffma2(w2[2 * i],     hv.x, b0);
                b1 = ffma2(w2[2 * i + 1], hv.y, b1);
            }
            float acc0 = lo2(a0) + hi2(a0) + lo2(a1) + hi2(a1) + xgc0;
            float acc1 = lo2(b0) + hi2(b0) + lo2(b1) + hi2(b1) + xgc1;

            float r0, r1;
            if (tid >= 200 && tid < 300) {         // cell gate g -> tanh
                r0 = tanh_f(acc0);
                r1 = tanh_f(acc1);
            } else {                               // i, f, o -> sigmoid
                r0 = sig_f(acc0);
                r1 = sig_f(acc1);
            }
            gbuf[0][tid] = r0;
            gbuf[1][tid] = r1;
        }
        __syncthreads();

        if (tid < 2 * H_) {
            const int b = tid / H_, j = tid - b * H_;
            float iv = gbuf[b][j];
            float fv = gbuf[b][H_ + j];
            float gv = gbuf[b][2 * H_ + j];
            float ov = gbuf[b][3 * H_ + j];
            c = fv * c + iv * gv;
            ((float*)hs[b])[j] = ov * tanh_f(c);
        }
        xgc0 = xgn0;
        xgc1 = xgn1;
        __syncthreads();
    }

    if (tid < 2) {
        float acc = b_fc[0];
        const float* hp = (const float*)hs[tid];
#pragma unroll 4
        for (int j = 0; j < H_; j++) acc += hp[j] * wfc_s[j];
        out[batch0 + tid] = acc;
    }
}

// ---------------------------------------------------------------------------
extern "C" void kernel_launch(void* const* d_in, const int* in_sizes, int n_in,
                              void* d_out, int out_size) {
    const float* x    = (const float*)d_in[0];
    const float* h0   = (const float*)d_in[1];
    const float* c0   = (const float*)d_in[2];
    const float* W_ih = (const float*)d_in[3];
    const float* W_hh = (const float*)d_in[4];
    const float* b_ih = (const float*)d_in[5];
    const float* b_hh = (const float*)d_in[6];
    const float* W_fc = (const float*)d_in[7];
    const float* b_fc = (const float*)d_in[8];
    float* out = (float*)d_out;

    cudaFuncSetAttribute(xg_kernel,
                         cudaFuncAttributeMaxDynamicSharedMemorySize, XG_SMEM);
    dim3 grid1(T_ / TT, B_);
    xg_kernel<<<grid1, 400, XG_SMEM>>>(x, W_ih, b_ih, b_hh);

    lstm_kernel<<<B_ / 2, 416>>>(h0, c0, W_hh, W_fc, b_fc, out);
}